// round 14
// baseline (speedup 1.0000x reference)
#include <cuda_runtime.h>
#include <cuda_fp16.h>
#include <math.h>
#include <limits.h>
#include <stdint.h>

#define KSEL 32
#define MAXN 4096
#define MAXS 65536
#define KTOT 768
#define CAP  3072
#define THRV 0.15f

extern __shared__ unsigned char dynsm[];

// ---------------- scratch ----------------------------------------------------
__device__ float  g_sim[(size_t)MAXN * MAXS];          // fallback paths only
__device__ __half g_At[(size_t)MAXN * KTOT];
__device__ __half g_Bt[(size_t)MAXS * KTOT];
__device__ float  g_candv[(size_t)MAXN * CAP];
__device__ int    g_candi[(size_t)MAXN * CAP];
__device__ unsigned int g_ccnt[MAXN];
__device__ float  g_topv[MAXN * KSEL];
__device__ int    g_topi[MAXN * KSEL];
__device__ int    g_tkfb[MAXN];
__device__ int    g_c1;
__device__ int    g_c5;

__device__ __forceinline__ uint32_t smem_u32(const void* p) {
    uint32_t a;
    asm("{ .reg .u64 t; cvta.to.shared.u64 t, %1; cvt.u32.u64 %0, t; }" : "=r"(a) : "l"(p));
    return a;
}

#define LDSM_X4(r0, r1, r2, r3, addr)                                          \
    asm volatile("ldmatrix.sync.aligned.m8n8.x4.shared.b16 {%0,%1,%2,%3}, [%4];" \
                 : "=r"(r0), "=r"(r1), "=r"(r2), "=r"(r3) : "r"(addr))

#define MMA16816(c, a, b)                                                      \
    asm volatile("mma.sync.aligned.m16n8k16.row.col.f32.f16.f16.f32 "          \
                 "{%0,%1,%2,%3}, {%4,%5,%6,%7}, {%8,%9}, {%0,%1,%2,%3};"       \
                 : "+f"((c)[0]), "+f"((c)[1]), "+f"((c)[2]), "+f"((c)[3])      \
                 : "r"((a)[0]), "r"((a)[1]), "r"((a)[2]), "r"((a)[3]),         \
                   "r"((b)[0]), "r"((b)[1]))

#define CP_ASYNC16(dst, src)                                                   \
    asm volatile("cp.async.cg.shared.global [%0], [%1], 16;" :: "r"(dst), "l"(src))
#define CP_COMMIT() asm volatile("cp.async.commit_group;" ::: "memory")
#define CP_WAIT2()  asm volatile("cp.async.wait_group 2;" ::: "memory")

// ---------------------------------------------------------------------------
// Conversions (fp16 3-term split) — vectorized
// ---------------------------------------------------------------------------
__global__ void knn_convA(const float* __restrict__ A, int N, int D) {
    int i4 = blockIdx.x * blockDim.x + threadIdx.x;
    if (i4 * 4 >= N * D) return;
    int i = i4 * 4;
    int m = i / D, k = i - m * D;
    float4 a4 = *(const float4*)(A + i);
    float av[4] = {a4.x, a4.y, a4.z, a4.w};
    size_t ro = (size_t)m * KTOT + k;
#pragma unroll
    for (int q = 0; q < 4; q++) {
        float a = av[q];
        __half h = __float2half_rn(a);
        float hf = __half2float(h);
        g_At[ro + q] = h;
        g_At[ro + 256 + q] = __float2half_rn((a - hf) * 64.f);
        g_At[ro + 512 + q] = __float2half_rn(hf * (1.f / 32.f));
    }
}

__global__ void knn_convB(const float* __restrict__ B, int D, int S) {
    __shared__ float t[32][33];
    int s0 = blockIdx.x * 32, k0 = blockIdx.y * 32;
    t[threadIdx.y][threadIdx.x] = B[(size_t)(k0 + threadIdx.y) * S + s0 + threadIdx.x];
    t[threadIdx.y + 16][threadIdx.x] =
        B[(size_t)(k0 + threadIdx.y + 16) * S + s0 + threadIdx.x];
    __syncthreads();
    int kp = threadIdx.x & 15;
    int sl = threadIdx.y * 2 + (threadIdx.x >> 4);
    int k = k0 + kp * 2, s = s0 + sl;
    float b0 = t[kp * 2][sl], b1 = t[kp * 2 + 1][sl];
    __half h0 = __float2half_rn(b0), h1 = __float2half_rn(b1);
    float f0 = __half2float(h0), f1 = __half2float(h1);
    size_t ro = (size_t)s * KTOT + k;
    *(__half2*)&g_Bt[ro]       = __halves2half2(h0, h1);
    *(__half2*)&g_Bt[ro + 256] = __halves2half2(__float2half_rn(f0 * (1.f / 64.f)),
                                                __float2half_rn(f1 * (1.f / 64.f)));
    *(__half2*)&g_Bt[ro + 512] = __halves2half2(__float2half_rn((b0 - f0) * 32.f),
                                                __float2half_rn((b1 - f1) * 32.f));
}

// ---------------------------------------------------------------------------
// mma.sync fp16 GEMM + fused threshold-gather (R11 mainloop, 4 stages, &3 idx)
// ---------------------------------------------------------------------------
#define BMT 128
#define BNT 128
#define BKT 32
#define ROWB 80
#define TSZ  (BMT * ROWB)
#define STGB (2 * TSZ)
#define NSTG 4
#define KT   (KTOT / BKT)

__device__ __forceinline__ void gload_stage(uint32_t sbase, int m0, int n0,
                                            int kb, int t) {
    int r = t >> 2, cch = t & 3;
    uint32_t dstA = sbase + r * ROWB + cch * 16;
    const __half* srcA = g_At + (size_t)(m0 + r) * KTOT + kb + cch * 8;
    CP_ASYNC16(dstA, srcA);
    uint32_t dstB = sbase + TSZ + r * ROWB + cch * 16;
    const __half* srcB = g_Bt + (size_t)(n0 + r) * KTOT + kb + cch * 8;
    CP_ASYNC16(dstB, srcB);
}

__device__ __forceinline__ void cand_push(int row, int col, float v) {
    if (v > THRV) {
        unsigned p = atomicAdd(&g_ccnt[row], 1u);
        if (p < CAP) {
            g_candv[(size_t)row * CAP + p] = v;
            g_candi[(size_t)row * CAP + p] = col;
        }
    }
}

__global__ __launch_bounds__(512, 2) void knn_gemm_mma(int S) {
    const uint32_t base = smem_u32(dynsm);
    const int t = threadIdx.x;
    const int wid = t >> 5, l = t & 31;
    const int wm = wid & 3, wn = wid >> 2;
    const int m0 = blockIdx.x * BMT;
    const int n0 = blockIdx.y * BNT;

    float c[2][4][4];
#pragma unroll
    for (int i = 0; i < 2; i++)
#pragma unroll
        for (int j = 0; j < 4; j++)
#pragma unroll
            for (int q = 0; q < 4; q++) c[i][j][q] = 0.f;

    const uint32_t a_row = wm * 32 + (l & 15);
    const uint32_t a_col = (l >> 4) * 8;
    const uint32_t b_row = wn * 32 + (l & 7) + ((l >> 4) & 1) * 8;
    const uint32_t b_col = ((l >> 3) & 1) * 8;

    gload_stage(base, m0, n0, 0, t);                  CP_COMMIT();
    gload_stage(base + STGB, m0, n0, BKT, t);         CP_COMMIT();
    gload_stage(base + 2 * STGB, m0, n0, 2 * BKT, t); CP_COMMIT();

    for (int kt = 0; kt < KT; kt++) {
        CP_WAIT2();
        __syncthreads();
        int nxt = kt + 3;
        if (nxt < KT) gload_stage(base + (nxt & 3) * STGB, m0, n0, nxt * BKT, t);
        CP_COMMIT();

        const uint32_t sa = base + (kt & 3) * STGB;
        const uint32_t sb = sa + TSZ;
#pragma unroll
        for (int ks = 0; ks < 2; ks++) {
            uint32_t a[2][4], b[4][2];
#pragma unroll
            for (int mt = 0; mt < 2; mt++) {
                uint32_t ad = sa + (a_row + mt * 16) * ROWB + (a_col + ks * 16) * 2;
                LDSM_X4(a[mt][0], a[mt][1], a[mt][2], a[mt][3], ad);
            }
#pragma unroll
            for (int np = 0; np < 2; np++) {
                uint32_t bd = sb + (b_row + np * 16) * ROWB + (b_col + ks * 16) * 2;
                uint32_t r0, r1, r2, r3;
                LDSM_X4(r0, r1, r2, r3, bd);
                b[np * 2][0] = r0; b[np * 2][1] = r1;
                b[np * 2 + 1][0] = r2; b[np * 2 + 1][1] = r3;
            }
#pragma unroll
            for (int mt = 0; mt < 2; mt++)
#pragma unroll
                for (int nt = 0; nt < 4; nt++)
                    MMA16816(c[mt][nt], a[mt], b[nt]);
        }
    }

    const int grp = l >> 2, qd = l & 3;
#pragma unroll
    for (int mt = 0; mt < 2; mt++) {
        int m = m0 + wm * 32 + mt * 16 + grp;
#pragma unroll
        for (int nt = 0; nt < 4; nt++) {
            int n = n0 + wn * 32 + nt * 8 + qd * 2;
            cand_push(m,     n,     c[mt][nt][0]);
            cand_push(m,     n + 1, c[mt][nt][1]);
            cand_push(m + 8, n,     c[mt][nt][2]);
            cand_push(m + 8, n + 1, c[mt][nt][3]);
        }
    }
}

// ---------------------------------------------------------------------------
// Fused select+scatter (fast path; flags unusable rows)
// ---------------------------------------------------------------------------
__global__ __launch_bounds__(256) void knn_sel_scatter(
    const int* __restrict__ qlabels, const int* __restrict__ tlabels,
    float* __restrict__ out, int C) {
    __shared__ float cv[CAP];
    __shared__ int   ci[CAP];
    __shared__ float p[1024];
    __shared__ float swv[8];
    __shared__ int   swi[8], swp[8];
    __shared__ float selv[KSEL];
    __shared__ int   seli[KSEL];
    __shared__ float rv[256];
    __shared__ int   ri[256];
    const int row = blockIdx.x;
    const int t = threadIdx.x, w = t >> 5, l = t & 31;
    const float NEGINF = __int_as_float(0xff800000);

    unsigned cnt = g_ccnt[row];
    if (cnt < KSEL || cnt > CAP) {
        if (t == 0) g_tkfb[row] = 1;
        return;
    }
    const int M = (int)cnt;
    for (int i = t; i < M; i += 256) {
        cv[i] = g_candv[(size_t)row * CAP + i];
        ci[i] = g_candi[(size_t)row * CAP + i];
    }
    for (int i = t; i < C; i += 256) p[i] = 0.f;
    __syncthreads();

    for (int sel = 0; sel < KSEL; sel++) {
        float v = NEGINF; int idx = INT_MAX, pos = -1;
        for (int i = t; i < M; i += 256) {
            float u = cv[i]; int ui = ci[i];
            if (u > v || (u == v && ui < idx)) { v = u; idx = ui; pos = i; }
        }
#pragma unroll
        for (int off = 16; off; off >>= 1) {
            float ov = __shfl_xor_sync(0xffffffffu, v, off);
            int   oi = __shfl_xor_sync(0xffffffffu, idx, off);
            int   op = __shfl_xor_sync(0xffffffffu, pos, off);
            if (ov > v || (ov == v && oi < idx)) { v = ov; idx = oi; pos = op; }
        }
        if (l == 0) { swv[w] = v; swi[w] = idx; swp[w] = pos; }
        __syncthreads();
        if (w == 0) {
            float v2 = (l < 8) ? swv[l] : NEGINF;
            int i2 = (l < 8) ? swi[l] : INT_MAX;
            int p2 = (l < 8) ? swp[l] : -1;
#pragma unroll
            for (int off = 4; off; off >>= 1) {
                float ov = __shfl_xor_sync(0xffffffffu, v2, off);
                int   oi = __shfl_xor_sync(0xffffffffu, i2, off);
                int   op = __shfl_xor_sync(0xffffffffu, p2, off);
                if (ov > v2 || (ov == v2 && oi < i2)) { v2 = ov; i2 = oi; p2 = op; }
            }
            if (l == 0) {
                selv[sel] = v2; seli[sel] = i2;
                cv[p2] = NEGINF; ci[p2] = INT_MAX;
            }
        }
        __syncthreads();
    }

    if (t == 0) {
        for (int j = 0; j < KSEL; j++)
            p[qlabels[seli[j]]] += expf(selv[j] / 0.07f);
    }
    __syncthreads();
    for (int i = t; i < C; i += 256) out[(size_t)row * C + i] = p[i];

    const int label = tlabels[row];
    int c1 = 0, c5 = 0;
    for (int sel = 0; sel < 5; sel++) {
        float bv = NEGINF; int bi = INT_MAX;
        for (int i = t; i < C; i += 256) {
            float v = p[i];
            if (v > bv || (v == bv && i < bi)) { bv = v; bi = i; }
        }
        rv[t] = bv; ri[t] = bi;
        __syncthreads();
        for (int str = 128; str > 0; str >>= 1) {
            if (t < str) {
                if (rv[t + str] > rv[t] || (rv[t + str] == rv[t] && ri[t + str] < ri[t])) {
                    rv[t] = rv[t + str]; ri[t] = ri[t + str];
                }
            }
            __syncthreads();
        }
        if (t == 0) {
            if (ri[0] == label) { c5++; if (sel == 0) c1++; }
            p[ri[0]] = NEGINF;
        }
        __syncthreads();
    }
    if (t == 0) {
        if (c1) atomicAdd(&g_c1, 1);
        if (c5) atomicAdd(&g_c5, 1);
    }
}

// ---------------------------------------------------------------------------
// Grid-stride fallback: recompute flagged rows' sims (cheap flag scan).
// ---------------------------------------------------------------------------
__global__ __launch_bounds__(256) void knn_row_gemv(const float* __restrict__ A,
                                                    const float* __restrict__ B,
                                                    int D, int S, int N) {
    __shared__ float a[256];
    const int t = threadIdx.x;
    for (int row = blockIdx.x; row < N; row += gridDim.x) {
        if (__ldg(&g_tkfb[row]) == 0) continue;
        for (int k = t; k < D; k += 256) a[k] = A[(size_t)row * D + k];
        __syncthreads();
        for (int s = t; s < S; s += 256) {
            float acc = 0.f;
            for (int k = 0; k < D; k++) acc += a[k] * B[(size_t)k * S + s];
            g_sim[(size_t)row * S + s] = acc;
        }
        __syncthreads();
    }
}

// ---------------------------------------------------------------------------
// Per-row exact insertion top-32 body (used by fallback + non-fast path)
// ---------------------------------------------------------------------------
#define TKNT 256
__device__ __forceinline__ void warg(float& v, int& idx, int& ln) {
#pragma unroll
    for (int off = 16; off; off >>= 1) {
        float ov = __shfl_xor_sync(0xffffffffu, v, off);
        int   oi = __shfl_xor_sync(0xffffffffu, idx, off);
        int   ol = __shfl_xor_sync(0xffffffffu, ln, off);
        if (ov > v || (ov == v && oi < idx)) { v = ov; idx = oi; ln = ol; }
    }
}

__device__ void topk_row_body(int row, int S) {
    float* sv = (float*)dynsm;
    int*   si = (int*)(dynsm + TKNT * KSEL * 4);
    float* wv2 = (float*)(dynsm + TKNT * KSEL * 8);
    int*   wi2 = (int*)(dynsm + TKNT * KSEL * 8 + 1024);

    const int t = threadIdx.x;
    const int w = t >> 5, l = t & 31;
    const float* srow = g_sim + (size_t)row * S;
    const float NEGINF = __int_as_float(0xff800000);

    float gmin[8];
#pragma unroll
    for (int it = 0; it < 8; it++) {
        int s = it * (TKNT * 4) + t * 4;
        float4 v4 = *(const float4*)(srow + s);
        float vq[4] = {v4.x, v4.y, v4.z, v4.w};
#pragma unroll
        for (int q = 0; q < 4; q++) {
            int j = it * 4 + q;
            sv[j * TKNT + t] = vq[q];
            si[j * TKNT + t] = s + q;
        }
        gmin[it] = fminf(fminf(vq[0], vq[1]), fminf(vq[2], vq[3]));
    }
    float lmin = gmin[0];
#pragma unroll
    for (int g = 1; g < 8; g++) lmin = fminf(lmin, gmin[g]);

    const int ITER = S / (TKNT * 4);
    for (int it = 8; it < ITER; it++) {
        int s = it * (TKNT * 4) + t * 4;
        float4 v4 = *(const float4*)(srow + s);
        float vq[4] = {v4.x, v4.y, v4.z, v4.w};
#pragma unroll
        for (int q = 0; q < 4; q++) {
            float v = vq[q];
            if (v > lmin) {
                int gpos = 0; float m = gmin[0];
#pragma unroll
                for (int g = 1; g < 8; g++)
                    if (gmin[g] < m) { m = gmin[g]; gpos = g; }
                int jb = gpos * 4;
                float u0 = sv[(jb + 0) * TKNT + t];
                float u1 = sv[(jb + 1) * TKNT + t];
                float u2 = sv[(jb + 2) * TKNT + t];
                float u3 = sv[(jb + 3) * TKNT + t];
                int jm = 0; float mm = u0;
                if (u1 < mm) { mm = u1; jm = 1; }
                if (u2 < mm) { mm = u2; jm = 2; }
                if (u3 < mm) { mm = u3; jm = 3; }
                sv[(jb + jm) * TKNT + t] = v;
                si[(jb + jm) * TKNT + t] = s + q;
                u0 = (jm == 0) ? v : u0;
                u1 = (jm == 1) ? v : u1;
                u2 = (jm == 2) ? v : u2;
                u3 = (jm == 3) ? v : u3;
                float ng = fminf(fminf(u0, u1), fminf(u2, u3));
#pragma unroll
                for (int g = 0; g < 8; g++) if (g == gpos) gmin[g] = ng;
                lmin = gmin[0];
#pragma unroll
                for (int g = 1; g < 8; g++) lmin = fminf(lmin, gmin[g]);
            }
        }
    }
    __syncthreads();

    float bv = NEGINF; int bj = 0, bidx = INT_MAX;
#pragma unroll
    for (int j = 0; j < KSEL; j++) {
        float u = sv[j * TKNT + t]; int ui = si[j * TKNT + t];
        if (u > bv || (u == bv && ui < bidx)) { bv = u; bj = j; bidx = ui; }
    }
    for (int sel = 0; sel < KSEL; sel++) {
        float v = bv; int idx = bidx; int ln = l;
        warg(v, idx, ln);
        if (l == 0) { wv2[w * KSEL + sel] = v; wi2[w * KSEL + sel] = idx; }
        if (l == ln) {
            sv[bj * TKNT + t] = NEGINF; si[bj * TKNT + t] = INT_MAX;
            bv = NEGINF; bj = 0; bidx = INT_MAX;
#pragma unroll
            for (int j = 0; j < KSEL; j++) {
                float u = sv[j * TKNT + t]; int ui = si[j * TKNT + t];
                if (u > bv || (u == bv && ui < bidx)) { bv = u; bj = j; bidx = ui; }
            }
        }
        __syncwarp();
    }
    __syncthreads();

    if (w == 0) {
        int head = 0;
        float hv = NEGINF; int hi = INT_MAX;
        if (l < 8) { hv = wv2[l * KSEL]; hi = wi2[l * KSEL]; }
        for (int sel = 0; sel < KSEL; sel++) {
            float v = hv; int idx = hi; int ln = l;
            warg(v, idx, ln);
            if (l == 0) {
                g_topv[row * KSEL + sel] = v;
                g_topi[row * KSEL + sel] = idx;
            }
            if (l == ln) {
                head++;
                if (l < 8 && head < KSEL) { hv = wv2[l * KSEL + head]; hi = wi2[l * KSEL + head]; }
                else { hv = NEGINF; hi = INT_MAX; }
            }
            __syncwarp();
        }
    }
    __syncthreads();
}

__global__ __launch_bounds__(TKNT) void knn_topk(int S, int N, int force) {
    for (int row = blockIdx.x; row < N; row += gridDim.x) {
        if (!force && __ldg(&g_tkfb[row]) == 0) continue;
        topk_row_body(row, S);
    }
}

// ---------------------------------------------------------------------------
// Scatter from g_topv/g_topi (grid-stride; flagged rows unless force)
// ---------------------------------------------------------------------------
__global__ __launch_bounds__(128) void knn_scatter(const int* __restrict__ qlabels,
                                                   const int* __restrict__ tlabels,
                                                   float* __restrict__ out, int C,
                                                   int N, int force) {
    __shared__ float p[1024];
    __shared__ float wv[KSEL];
    __shared__ int wc[KSEL];
    __shared__ float rv[128];
    __shared__ int ri[128];
    const int t = threadIdx.x;
    const float NEGINF = __int_as_float(0xff800000);

    for (int row = blockIdx.x; row < N; row += gridDim.x) {
        if (!force && __ldg(&g_tkfb[row]) == 0) continue;

        for (int i = t; i < C; i += 128) p[i] = 0.f;
        if (t < KSEL) {
            float d = g_topv[row * KSEL + t];
            wv[t] = expf(d / 0.07f);
            wc[t] = qlabels[g_topi[row * KSEL + t]];
        }
        __syncthreads();
        if (t == 0) for (int j = 0; j < KSEL; j++) p[wc[j]] += wv[j];
        __syncthreads();
        for (int i = t; i < C; i += 128) out[(size_t)row * C + i] = p[i];

        const int label = tlabels[row];
        int c1 = 0, c5 = 0;
        for (int sel = 0; sel < 5; sel++) {
            float bv = NEGINF; int bi = INT_MAX;
            for (int i = t; i < C; i += 128) {
                float v = p[i];
                if (v > bv || (v == bv && i < bi)) { bv = v; bi = i; }
            }
            rv[t] = bv; ri[t] = bi;
            __syncthreads();
            for (int str = 64; str > 0; str >>= 1) {
                if (t < str) {
                    if (rv[t + str] > rv[t] || (rv[t + str] == rv[t] && ri[t + str] < ri[t])) {
                        rv[t] = rv[t + str]; ri[t] = ri[t + str];
                    }
                }
                __syncthreads();
            }
            if (t == 0) {
                if (ri[0] == label) { c5++; if (sel == 0) c1++; }
                p[ri[0]] = NEGINF;
            }
            __syncthreads();
        }
        if (t == 0) {
            if (c1) atomicAdd(&g_c1, 1);
            if (c5) atomicAdd(&g_c5, 1);
        }
        __syncthreads();
    }
}

// ---------------------------------------------------------------------------
// Fallback fp32 GEMM (unexpected dims) — writes g_sim
// ---------------------------------------------------------------------------
#define BM 64
#define BN 64
#define BK 16
__global__ __launch_bounds__(256) void knn_gemm(const float* __restrict__ A,
                                                const float* __restrict__ B,
                                                int N, int D, int S) {
    __shared__ float As[BK][BM];
    __shared__ float Bs[BK][BN];
    const int tid = threadIdx.x;
    const int tx = tid & 15, ty = tid >> 4;
    const int s0 = blockIdx.x * BN, m0 = blockIdx.y * BM;
    const int am = tid >> 2, ak = (tid & 3) << 2;
    const int bkr = tid >> 4, bc = (tid & 15) << 2;
    float acc[4][4];
#pragma unroll
    for (int i = 0; i < 4; i++)
#pragma unroll
        for (int j = 0; j < 4; j++) acc[i][j] = 0.f;
    const float* aptr = A + (size_t)(m0 + am) * D + ak;
    const float* bptr = B + (size_t)bkr * S + s0 + bc;
    for (int k0 = 0; k0 < D; k0 += BK) {
        float4 av = *(const float4*)(aptr + k0);
        float4 bv = *(const float4*)(bptr + (size_t)k0 * S);
        __syncthreads();
        As[ak + 0][am] = av.x; As[ak + 1][am] = av.y;
        As[ak + 2][am] = av.z; As[ak + 3][am] = av.w;
        *(float4*)&Bs[bkr][bc] = bv;
        __syncthreads();
#pragma unroll
        for (int kk = 0; kk < BK; kk++) {
            float4 a = *(const float4*)&As[kk][ty << 2];
            float4 b = *(const float4*)&Bs[kk][tx << 2];
            acc[0][0] += a.x * b.x; acc[0][1] += a.x * b.y; acc[0][2] += a.x * b.z; acc[0][3] += a.x * b.w;
            acc[1][0] += a.y * b.x; acc[1][1] += a.y * b.y; acc[1][2] += a.y * b.z; acc[1][3] += a.y * b.w;
            acc[2][0] += a.z * b.x; acc[2][1] += a.z * b.y; acc[2][2] += a.z * b.z; acc[2][3] += a.z * b.w;
            acc[3][0] += a.w * b.x; acc[3][1] += a.w * b.y; acc[3][2] += a.w * b.z; acc[3][3] += a.w * b.w;
        }
    }
#pragma unroll
    for (int i = 0; i < 4; i++) {
        float4 v = make_float4(acc[i][0], acc[i][1], acc[i][2], acc[i][3]);
        *(float4*)(g_sim + (size_t)(m0 + (ty << 2) + i) * S + s0 + (tx << 2)) = v;
    }
}

__global__ void knn_init(int N) {
    int i = blockIdx.x * blockDim.x + threadIdx.x;
    if (i < N) { g_tkfb[i] = 0; g_ccnt[i] = 0u; }
    if (i == 0) { g_c1 = 0; g_c5 = 0; }
}
__global__ void knn_final(float* out, size_t off, int N) {
    out[off] = 100.f * (float)g_c1 / (float)N;
    out[off + 1] = 100.f * (float)g_c5 / (float)N;
}

// ---------------------------------------------------------------------------
extern "C" void kernel_launch(void* const* d_in, const int* in_sizes, int n_in,
                              void* d_out, int out_size) {
    const float* feats = (const float*)d_in[0];
    const int* tlabels = (const int*)d_in[1];
    const float* queue = (const float*)d_in[2];
    const int* qlabels = (const int*)d_in[3];

    const int N = in_sizes[1];
    const int D = in_sizes[0] / N;
    const int S = in_sizes[3];
    float* out = (float*)d_out;

    long long os = out_size;
    int C;
    if (N > 0 && (os - 2) > 0 && ((os - 2) % N) == 0) C = (int)((os - 2) / N);
    else C = (int)(os / N);

    const int tk_smem = TKNT * KSEL * 8 + 2048;
    cudaFuncSetAttribute(knn_topk, cudaFuncAttributeMaxDynamicSharedMemorySize, tk_smem);

    const bool fast = (D == 256 && (N % BMT) == 0 && (S % BNT) == 0 && (S % 1024) == 0);

    knn_init<<<(N + 255) / 256, 256>>>(N);

    if (fast) {
        knn_convA<<<(N * D / 4 + 255) / 256, 256>>>(feats, N, D);
        knn_convB<<<dim3(S / 32, D / 32), dim3(32, 16)>>>(queue, D, S);
        cudaFuncSetAttribute(knn_gemm_mma,
                             cudaFuncAttributeMaxDynamicSharedMemorySize, NSTG * STGB);
        knn_gemm_mma<<<dim3(N / BMT, S / BNT), 512, NSTG * STGB>>>(S);
        knn_sel_scatter<<<N, 256>>>(qlabels, tlabels, out, C);       // fast path
        knn_row_gemv<<<148, 256>>>(feats, queue, D, S, N);           // flag scan
        knn_topk<<<148, TKNT, tk_smem>>>(S, N, 0);                   // flag scan
        knn_scatter<<<148, 128>>>(qlabels, tlabels, out, C, N, 0);   // flag scan
    } else {
        dim3 gg(S / BN, N / BM);
        knn_gemm<<<gg, 256>>>(feats, queue, N, D, S);
        knn_topk<<<N, TKNT, tk_smem>>>(S, N, 1);
        knn_scatter<<<N, 128>>>(qlabels, tlabels, out, C, N, 1);
    }

    if ((size_t)N * C + 2 <= (size_t)out_size)
        knn_final<<<1, 1>>>(out, (size_t)N * C, N);
}

// round 15
// speedup vs baseline: 1.0175x; 1.0175x over previous
#include <cuda_runtime.h>
#include <cuda_fp16.h>
#include <math.h>
#include <limits.h>
#include <stdint.h>

#define KSEL 32
#define MAXN 4096
#define MAXS 65536
#define KTOT 768
#define CAP  3072
#define THRV 0.15f

// single shared dynamic-smem symbol (gemm + fallback topk)
extern __shared__ unsigned char dynsm[];

// ---------------- scratch (static __device__ = sanctioned alloc-free) -------
__device__ float  g_sim[(size_t)MAXN * MAXS];          // only used by fallback paths
__device__ __half g_At[(size_t)MAXN * KTOT];
__device__ __half g_Bt[(size_t)MAXS * KTOT];
__device__ float  g_candv[(size_t)MAXN * CAP];         // fused-gather candidates
__device__ int    g_candi[(size_t)MAXN * CAP];
__device__ unsigned int g_ccnt[MAXN];
__device__ float  g_topv[MAXN * KSEL];
__device__ int    g_topi[MAXN * KSEL];
__device__ int    g_tkfb[MAXN];                        // fallback flags
__device__ int    g_c1;
__device__ int    g_c5;

__device__ __forceinline__ uint32_t smem_u32(const void* p) {
    uint32_t a;
    asm("{ .reg .u64 t; cvta.to.shared.u64 t, %1; cvt.u32.u64 %0, t; }" : "=r"(a) : "l"(p));
    return a;
}

#define LDSM_X4(r0, r1, r2, r3, addr)                                          \
    asm volatile("ldmatrix.sync.aligned.m8n8.x4.shared.b16 {%0,%1,%2,%3}, [%4];" \
                 : "=r"(r0), "=r"(r1), "=r"(r2), "=r"(r3) : "r"(addr))

#define MMA16816(c, a, b)                                                      \
    asm volatile("mma.sync.aligned.m16n8k16.row.col.f32.f16.f16.f32 "          \
                 "{%0,%1,%2,%3}, {%4,%5,%6,%7}, {%8,%9}, {%0,%1,%2,%3};"       \
                 : "+f"((c)[0]), "+f"((c)[1]), "+f"((c)[2]), "+f"((c)[3])      \
                 : "r"((a)[0]), "r"((a)[1]), "r"((a)[2]), "r"((a)[3]),         \
                   "r"((b)[0]), "r"((b)[1]))

#define CP_ASYNC16(dst, src)                                                   \
    asm volatile("cp.async.cg.shared.global [%0], [%1], 16;" :: "r"(dst), "l"(src))
#define CP_COMMIT() asm volatile("cp.async.commit_group;" ::: "memory")
#define CP_WAIT2()  asm volatile("cp.async.wait_group 2;" ::: "memory")

// ---------------------------------------------------------------------------
// Conversions (fp16 3-term split) — exact R11 versions
// ---------------------------------------------------------------------------
__global__ void knn_convA(const float* __restrict__ A, int N, int D) {
    int i = blockIdx.x * blockDim.x + threadIdx.x;
    if (i >= N * D) return;
    int m = i / D, k = i - m * D;
    float a = A[i];
    __half h = __float2half_rn(a);
    float hf = __half2float(h);
    __half l = __float2half_rn((a - hf) * 64.f);
    __half h3 = __float2half_rn(hf * (1.f / 32.f));
    size_t ro = (size_t)m * KTOT;
    g_At[ro + k] = h;
    g_At[ro + 256 + k] = l;
    g_At[ro + 512 + k] = h3;
}

__global__ void knn_convB(const float* __restrict__ B, int D, int S) {
    __shared__ float t[32][33];
    int s0 = blockIdx.x * 32, k0 = blockIdx.y * 32;
    t[threadIdx.y][threadIdx.x] = B[(size_t)(k0 + threadIdx.y) * S + s0 + threadIdx.x];
    __syncthreads();
    int k = k0 + threadIdx.x, s = s0 + threadIdx.y;
    float b = t[threadIdx.x][threadIdx.y];
    __half h = __float2half_rn(b);
    float hf = __half2float(h);
    __half h2 = __float2half_rn(hf * (1.f / 64.f));
    __half l3 = __float2half_rn((b - hf) * 32.f);
    size_t ro = (size_t)s * KTOT;
    g_Bt[ro + k] = h;
    g_Bt[ro + 256 + k] = h2;
    g_Bt[ro + 512 + k] = l3;
}

// ---------------------------------------------------------------------------
// mma.sync fp16 GEMM with FUSED threshold-gather epilogue (early-out added).
// CTA 128x128, BK=32, 512 threads (16 warps, 4Mx4N), warp tile 32x32,
// 4-stage cp.async (&3 indexing), 2 CTAs/SM.
// ---------------------------------------------------------------------------
#define BMT 128
#define BNT 128
#define BKT 32
#define ROWB 80
#define TSZ  (BMT * ROWB)
#define STGB (2 * TSZ)
#define NSTG 4
#define KT   (KTOT / BKT)

__device__ __forceinline__ void gload_stage(uint32_t sbase, int m0, int n0,
                                            int kb, int t) {
    int r = t >> 2, cch = t & 3;
    uint32_t dstA = sbase + r * ROWB + cch * 16;
    const __half* srcA = g_At + (size_t)(m0 + r) * KTOT + kb + cch * 8;
    CP_ASYNC16(dstA, srcA);
    uint32_t dstB = sbase + TSZ + r * ROWB + cch * 16;
    const __half* srcB = g_Bt + (size_t)(n0 + r) * KTOT + kb + cch * 8;
    CP_ASYNC16(dstB, srcB);
}

__device__ __forceinline__ void cand_push(int row, int col, float v) {
    if (v > THRV) {
        unsigned p = atomicAdd(&g_ccnt[row], 1u);
        if (p < CAP) {
            g_candv[(size_t)row * CAP + p] = v;
            g_candi[(size_t)row * CAP + p] = col;
        }
    }
}

__global__ __launch_bounds__(512, 2) void knn_gemm_mma(int S) {
    const uint32_t base = smem_u32(dynsm);
    const int t = threadIdx.x;
    const int wid = t >> 5, l = t & 31;
    const int wm = wid & 3, wn = wid >> 2;
    const int m0 = blockIdx.x * BMT;
    const int n0 = blockIdx.y * BNT;

    float c[2][4][4];
#pragma unroll
    for (int i = 0; i < 2; i++)
#pragma unroll
        for (int j = 0; j < 4; j++)
#pragma unroll
            for (int q = 0; q < 4; q++) c[i][j][q] = 0.f;

    const uint32_t a_row = wm * 32 + (l & 15);
    const uint32_t a_col = (l >> 4) * 8;
    const uint32_t b_row = wn * 32 + (l & 7) + ((l >> 4) & 1) * 8;
    const uint32_t b_col = ((l >> 3) & 1) * 8;

    gload_stage(base, m0, n0, 0, t);                  CP_COMMIT();
    gload_stage(base + STGB, m0, n0, BKT, t);         CP_COMMIT();
    gload_stage(base + 2 * STGB, m0, n0, 2 * BKT, t); CP_COMMIT();

    for (int kt = 0; kt < KT; kt++) {
        CP_WAIT2();
        __syncthreads();
        int nxt = kt + 3;
        if (nxt < KT) gload_stage(base + (nxt & 3) * STGB, m0, n0, nxt * BKT, t);
        CP_COMMIT();

        const uint32_t sa = base + (kt & 3) * STGB;
        const uint32_t sb = sa + TSZ;
#pragma unroll
        for (int ks = 0; ks < 2; ks++) {
            uint32_t a[2][4], b[4][2];
#pragma unroll
            for (int mt = 0; mt < 2; mt++) {
                uint32_t ad = sa + (a_row + mt * 16) * ROWB + (a_col + ks * 16) * 2;
                LDSM_X4(a[mt][0], a[mt][1], a[mt][2], a[mt][3], ad);
            }
#pragma unroll
            for (int np = 0; np < 2; np++) {
                uint32_t bd = sb + (b_row + np * 16) * ROWB + (b_col + ks * 16) * 2;
                uint32_t r0, r1, r2, r3;
                LDSM_X4(r0, r1, r2, r3, bd);
                b[np * 2][0] = r0; b[np * 2][1] = r1;
                b[np * 2 + 1][0] = r2; b[np * 2 + 1][1] = r3;
            }
#pragma unroll
            for (int mt = 0; mt < 2; mt++)
#pragma unroll
                for (int nt = 0; nt < 4; nt++)
                    MMA16816(c[mt][nt], a[mt], b[nt]);
        }
    }

    // ---- fused epilogue with early-out: 87.6% of threads skip all pushes ----
    float mx = c[0][0][0];
#pragma unroll
    for (int mt = 0; mt < 2; mt++)
#pragma unroll
        for (int nt = 0; nt < 4; nt++)
#pragma unroll
            for (int q = 0; q < 4; q++) mx = fmaxf(mx, c[mt][nt][q]);

    if (mx > THRV) {
        const int grp = l >> 2, qd = l & 3;
#pragma unroll
        for (int mt = 0; mt < 2; mt++) {
            int m = m0 + wm * 32 + mt * 16 + grp;
#pragma unroll
            for (int nt = 0; nt < 4; nt++) {
                int n = n0 + wn * 32 + nt * 8 + qd * 2;
                cand_push(m,     n,     c[mt][nt][0]);
                cand_push(m,     n + 1, c[mt][nt][1]);
                cand_push(m + 8, n,     c[mt][nt][2]);
                cand_push(m + 8, n + 1, c[mt][nt][3]);
            }
        }
    }
}

// ---------------------------------------------------------------------------
// Selection: exact top-32 from gathered candidates (desc, index-asc ties).
// Flags rows whose candidate set is unusable (cnt<32 or overflow).
// ---------------------------------------------------------------------------
__global__ __launch_bounds__(256) void knn_sel(int S) {
    __shared__ float cv[CAP];
    __shared__ int   ci[CAP];
    __shared__ float swv[8];
    __shared__ int   swi[8], swp[8];
    const int row = blockIdx.x;
    const int t = threadIdx.x, w = t >> 5, l = t & 31;
    const float NEGINF = __int_as_float(0xff800000);

    unsigned cnt = g_ccnt[row];
    if (cnt < KSEL || cnt > CAP) {
        if (t == 0) g_tkfb[row] = 1;
        return;
    }
    const int M = (int)cnt;
    for (int i = t; i < M; i += 256) {
        cv[i] = g_candv[(size_t)row * CAP + i];
        ci[i] = g_candi[(size_t)row * CAP + i];
    }
    __syncthreads();

    for (int sel = 0; sel < KSEL; sel++) {
        float v = NEGINF; int idx = INT_MAX, pos = -1;
        for (int i = t; i < M; i += 256) {
            float u = cv[i]; int ui = ci[i];
            if (u > v || (u == v && ui < idx)) { v = u; idx = ui; pos = i; }
        }
#pragma unroll
        for (int off = 16; off; off >>= 1) {
            float ov = __shfl_xor_sync(0xffffffffu, v, off);
            int   oi = __shfl_xor_sync(0xffffffffu, idx, off);
            int   op = __shfl_xor_sync(0xffffffffu, pos, off);
            if (ov > v || (ov == v && oi < idx)) { v = ov; idx = oi; pos = op; }
        }
        if (l == 0) { swv[w] = v; swi[w] = idx; swp[w] = pos; }
        __syncthreads();
        if (w == 0) {
            float v2 = (l < 8) ? swv[l] : NEGINF;
            int i2 = (l < 8) ? swi[l] : INT_MAX;
            int p2 = (l < 8) ? swp[l] : -1;
#pragma unroll
            for (int off = 4; off; off >>= 1) {
                float ov = __shfl_xor_sync(0xffffffffu, v2, off);
                int   oi = __shfl_xor_sync(0xffffffffu, i2, off);
                int   op = __shfl_xor_sync(0xffffffffu, p2, off);
                if (ov > v2 || (ov == v2 && oi < i2)) { v2 = ov; i2 = oi; p2 = op; }
            }
            if (l == 0) {
                g_topv[row * KSEL + sel] = v2;
                g_topi[row * KSEL + sel] = i2;
                cv[p2] = NEGINF; ci[p2] = INT_MAX;
            }
        }
        __syncthreads();
    }
}

// ---------------------------------------------------------------------------
// Fallback stage 1: recompute sims (fp32) for flagged rows into g_sim.
// ---------------------------------------------------------------------------
__global__ __launch_bounds__(256) void knn_row_gemv(const float* __restrict__ A,
                                                    const float* __restrict__ B,
                                                    int D, int S) {
    const int row = blockIdx.x;
    if (g_tkfb[row] == 0) return;
    __shared__ float a[256];
    const int t = threadIdx.x;
    for (int k = t; k < D; k += 256) a[k] = A[(size_t)row * D + k];
    __syncthreads();
    for (int s = t; s < S; s += 256) {
        float acc = 0.f;
        for (int k = 0; k < D; k++) acc += a[k] * B[(size_t)k * S + s];
        g_sim[(size_t)row * S + s] = acc;
    }
}

// ---------------------------------------------------------------------------
// Fallback stage 2 / non-fast path: exact insertion top-32 over g_sim.
// ---------------------------------------------------------------------------
#define TKNT 256
__device__ __forceinline__ void warg(float& v, int& idx, int& ln) {
#pragma unroll
    for (int off = 16; off; off >>= 1) {
        float ov = __shfl_xor_sync(0xffffffffu, v, off);
        int   oi = __shfl_xor_sync(0xffffffffu, idx, off);
        int   ol = __shfl_xor_sync(0xffffffffu, ln, off);
        if (ov > v || (ov == v && oi < idx)) { v = ov; idx = oi; ln = ol; }
    }
}

__global__ __launch_bounds__(TKNT) void knn_topk(int S, int force) {
    const int row = blockIdx.x;
    if (!force && g_tkfb[row] == 0) return;

    float* sv = (float*)dynsm;
    int*   si = (int*)(dynsm + TKNT * KSEL * 4);
    float* wv2 = (float*)(dynsm + TKNT * KSEL * 8);
    int*   wi2 = (int*)(dynsm + TKNT * KSEL * 8 + 1024);

    const int t = threadIdx.x;
    const int w = t >> 5, l = t & 31;
    const float* srow = g_sim + (size_t)row * S;
    const float NEGINF = __int_as_float(0xff800000);

    float gmin[8];
#pragma unroll
    for (int it = 0; it < 8; it++) {
        int s = it * (TKNT * 4) + t * 4;
        float4 v4 = *(const float4*)(srow + s);
        float vq[4] = {v4.x, v4.y, v4.z, v4.w};
#pragma unroll
        for (int q = 0; q < 4; q++) {
            int j = it * 4 + q;
            sv[j * TKNT + t] = vq[q];
            si[j * TKNT + t] = s + q;
        }
        gmin[it] = fminf(fminf(vq[0], vq[1]), fminf(vq[2], vq[3]));
    }
    float lmin = gmin[0];
#pragma unroll
    for (int g = 1; g < 8; g++) lmin = fminf(lmin, gmin[g]);

    const int ITER = S / (TKNT * 4);
    for (int it = 8; it < ITER; it++) {
        int s = it * (TKNT * 4) + t * 4;
        float4 v4 = *(const float4*)(srow + s);
        float vq[4] = {v4.x, v4.y, v4.z, v4.w};
#pragma unroll
        for (int q = 0; q < 4; q++) {
            float v = vq[q];
            if (v > lmin) {
                int gpos = 0; float m = gmin[0];
#pragma unroll
                for (int g = 1; g < 8; g++)
                    if (gmin[g] < m) { m = gmin[g]; gpos = g; }
                int jb = gpos * 4;
                float u0 = sv[(jb + 0) * TKNT + t];
                float u1 = sv[(jb + 1) * TKNT + t];
                float u2 = sv[(jb + 2) * TKNT + t];
                float u3 = sv[(jb + 3) * TKNT + t];
                int jm = 0; float mm = u0;
                if (u1 < mm) { mm = u1; jm = 1; }
                if (u2 < mm) { mm = u2; jm = 2; }
                if (u3 < mm) { mm = u3; jm = 3; }
                sv[(jb + jm) * TKNT + t] = v;
                si[(jb + jm) * TKNT + t] = s + q;
                u0 = (jm == 0) ? v : u0;
                u1 = (jm == 1) ? v : u1;
                u2 = (jm == 2) ? v : u2;
                u3 = (jm == 3) ? v : u3;
                float ng = fminf(fminf(u0, u1), fminf(u2, u3));
#pragma unroll
                for (int g = 0; g < 8; g++) if (g == gpos) gmin[g] = ng;
                lmin = gmin[0];
#pragma unroll
                for (int g = 1; g < 8; g++) lmin = fminf(lmin, gmin[g]);
            }
        }
    }
    __syncthreads();

    float bv = NEGINF; int bj = 0, bidx = INT_MAX;
#pragma unroll
    for (int j = 0; j < KSEL; j++) {
        float u = sv[j * TKNT + t]; int ui = si[j * TKNT + t];
        if (u > bv || (u == bv && ui < bidx)) { bv = u; bj = j; bidx = ui; }
    }
    for (int sel = 0; sel < KSEL; sel++) {
        float v = bv; int idx = bidx; int ln = l;
        warg(v, idx, ln);
        if (l == 0) { wv2[w * KSEL + sel] = v; wi2[w * KSEL + sel] = idx; }
        if (l == ln) {
            sv[bj * TKNT + t] = NEGINF; si[bj * TKNT + t] = INT_MAX;
            bv = NEGINF; bj = 0; bidx = INT_MAX;
#pragma unroll
            for (int j = 0; j < KSEL; j++) {
                float u = sv[j * TKNT + t]; int ui = si[j * TKNT + t];
                if (u > bv || (u == bv && ui < bidx)) { bv = u; bj = j; bidx = ui; }
            }
        }
        __syncwarp();
    }
    __syncthreads();

    if (w == 0) {
        int head = 0;
        float hv = NEGINF; int hi = INT_MAX;
        if (l < 8) { hv = wv2[l * KSEL]; hi = wi2[l * KSEL]; }
        for (int sel = 0; sel < KSEL; sel++) {
            float v = hv; int idx = hi; int ln = l;
            warg(v, idx, ln);
            if (l == 0) {
                g_topv[row * KSEL + sel] = v;
                g_topi[row * KSEL + sel] = idx;
            }
            if (l == ln) {
                head++;
                if (l < 8 && head < KSEL) { hv = wv2[l * KSEL + head]; hi = wi2[l * KSEL + head]; }
                else { hv = NEGINF; hi = INT_MAX; }
            }
            __syncwarp();
        }
    }
}

// ---------------------------------------------------------------------------
// Fallback fp32 GEMM (only for unexpected dims) — writes g_sim
// ---------------------------------------------------------------------------
#define BM 64
#define BN 64
#define BK 16
__global__ __launch_bounds__(256) void knn_gemm(const float* __restrict__ A,
                                                const float* __restrict__ B,
                                                int N, int D, int S) {
    __shared__ float As[BK][BM];
    __shared__ float Bs[BK][BN];
    const int tid = threadIdx.x;
    const int tx = tid & 15, ty = tid >> 4;
    const int s0 = blockIdx.x * BN, m0 = blockIdx.y * BM;
    const int am = tid >> 2, ak = (tid & 3) << 2;
    const int bkr = tid >> 4, bc = (tid & 15) << 2;
    float acc[4][4];
#pragma unroll
    for (int i = 0; i < 4; i++)
#pragma unroll
        for (int j = 0; j < 4; j++) acc[i][j] = 0.f;
    const float* aptr = A + (size_t)(m0 + am) * D + ak;
    const float* bptr = B + (size_t)bkr * S + s0 + bc;
    for (int k0 = 0; k0 < D; k0 += BK) {
        float4 av = *(const float4*)(aptr + k0);
        float4 bv = *(const float4*)(bptr + (size_t)k0 * S);
        __syncthreads();
        As[ak + 0][am] = av.x; As[ak + 1][am] = av.y;
        As[ak + 2][am] = av.z; As[ak + 3][am] = av.w;
        *(float4*)&Bs[bkr][bc] = bv;
        __syncthreads();
#pragma unroll
        for (int kk = 0; kk < BK; kk++) {
            float4 a = *(const float4*)&As[kk][ty << 2];
            float4 b = *(const float4*)&Bs[kk][tx << 2];
            acc[0][0] += a.x * b.x; acc[0][1] += a.x * b.y; acc[0][2] += a.x * b.z; acc[0][3] += a.x * b.w;
            acc[1][0] += a.y * b.x; acc[1][1] += a.y * b.y; acc[1][2] += a.y * b.z; acc[1][3] += a.y * b.w;
            acc[2][0] += a.z * b.x; acc[2][1] += a.z * b.y; acc[2][2] += a.z * b.z; acc[2][3] += a.z * b.w;
            acc[3][0] += a.w * b.x; acc[3][1] += a.w * b.y; acc[3][2] += a.w * b.z; acc[3][3] += a.w * b.w;
        }
    }
#pragma unroll
    for (int i = 0; i < 4; i++) {
        float4 v = make_float4(acc[i][0], acc[i][1], acc[i][2], acc[i][3]);
        *(float4*)(g_sim + (size_t)(m0 + (ty << 2) + i) * S + s0 + (tx << 2)) = v;
    }
}

// ---------------------------------------------------------------------------
// Scatter + probs + top-5 accuracy (all rows, from g_topv/g_topi)
// ---------------------------------------------------------------------------
__global__ __launch_bounds__(128) void knn_scatter(const int* __restrict__ qlabels,
                                                   const int* __restrict__ tlabels,
                                                   float* __restrict__ out, int C, int N) {
    __shared__ float p[1024];
    __shared__ float wv[KSEL];
    __shared__ int wc[KSEL];
    __shared__ float rv[128];
    __shared__ int ri[128];
    const int row = blockIdx.x;
    const int t = threadIdx.x;
    const float NEGINF = __int_as_float(0xff800000);

    for (int i = t; i < C; i += 128) p[i] = 0.f;
    if (t < KSEL) {
        float d = g_topv[row * KSEL + t];
        wv[t] = expf(d / 0.07f);
        wc[t] = qlabels[g_topi[row * KSEL + t]];
    }
    __syncthreads();
    if (t == 0) for (int j = 0; j < KSEL; j++) p[wc[j]] += wv[j];
    __syncthreads();
    for (int i = t; i < C; i += 128) out[(size_t)row * C + i] = p[i];

    const int label = tlabels[row];
    int c1 = 0, c5 = 0;
    for (int sel = 0; sel < 5; sel++) {
        float bv = NEGINF; int bi = INT_MAX;
        for (int i = t; i < C; i += 128) {
            float v = p[i];
            if (v > bv || (v == bv && i < bi)) { bv = v; bi = i; }
        }
        rv[t] = bv; ri[t] = bi;
        __syncthreads();
        for (int str = 64; str > 0; str >>= 1) {
            if (t < str) {
                if (rv[t + str] > rv[t] || (rv[t + str] == rv[t] && ri[t + str] < ri[t])) {
                    rv[t] = rv[t + str]; ri[t] = ri[t + str];
                }
            }
            __syncthreads();
        }
        if (t == 0) {
            if (ri[0] == label) { c5++; if (sel == 0) c1++; }
            p[ri[0]] = NEGINF;
        }
        __syncthreads();
    }
    if (t == 0) {
        if (c1) atomicAdd(&g_c1, 1);
        if (c5) atomicAdd(&g_c5, 1);
    }
}

__global__ void knn_init(int N) {
    int i = blockIdx.x * blockDim.x + threadIdx.x;
    if (i < N) { g_tkfb[i] = 0; g_ccnt[i] = 0u; }
    if (i == 0) { g_c1 = 0; g_c5 = 0; }
}
__global__ void knn_final(float* out, size_t off, int N) {
    out[off] = 100.f * (float)g_c1 / (float)N;
    out[off + 1] = 100.f * (float)g_c5 / (float)N;
}

// ---------------------------------------------------------------------------
extern "C" void kernel_launch(void* const* d_in, const int* in_sizes, int n_in,
                              void* d_out, int out_size) {
    const float* feats = (const float*)d_in[0];
    const int* tlabels = (const int*)d_in[1];
    const float* queue = (const float*)d_in[2];
    const int* qlabels = (const int*)d_in[3];

    const int N = in_sizes[1];
    const int D = in_sizes[0] / N;
    const int S = in_sizes[3];
    float* out = (float*)d_out;

    long long os = out_size;
    int C;
    if (N > 0 && (os - 2) > 0 && ((os - 2) % N) == 0) C = (int)((os - 2) / N);
    else C = (int)(os / N);

    const int tk_smem = TKNT * KSEL * 8 + 2048;
    cudaFuncSetAttribute(knn_topk, cudaFuncAttributeMaxDynamicSharedMemorySize, tk_smem);

    const bool fast = (D == 256 && (N % BMT) == 0 && (S % BNT) == 0 && (S % 1024) == 0);

    knn_init<<<(N + 255) / 256, 256>>>(N);

    if (fast) {
        knn_convA<<<(N * D + 255) / 256, 256>>>(feats, N, D);
        knn_convB<<<dim3(S / 32, D / 32), dim3(32, 32)>>>(queue, D, S);
        cudaFuncSetAttribute(knn_gemm_mma,
                             cudaFuncAttributeMaxDynamicSharedMemorySize, NSTG * STGB);
        knn_gemm_mma<<<dim3(N / BMT, S / BNT), 512, NSTG * STGB>>>(S);
        knn_sel<<<N, 256>>>(S);                       // exact select from candidates
        knn_row_gemv<<<N, 256>>>(feats, queue, D, S); // fallback fill (flagged rows)
        knn_topk<<<N, TKNT, tk_smem>>>(S, 0);         // fallback select (flagged rows)
    } else {
        dim3 gg(S / BN, N / BM);
        knn_gemm<<<gg, 256>>>(feats, queue, N, D, S);
        knn_topk<<<N, TKNT, tk_smem>>>(S, 1);
    }

    knn_scatter<<<N, 128>>>(qlabels, tlabels, out, C, N);
    if ((size_t)N * C + 2 <= (size_t)out_size)
        knn_final<<<1, 1>>>(out, (size_t)N * C, N);
}

// round 16
// speedup vs baseline: 1.0858x; 1.0671x over previous
#include <cuda_runtime.h>
#include <cuda_fp16.h>
#include <math.h>
#include <limits.h>
#include <stdint.h>

#define KSEL 32
#define MAXN 4096
#define MAXS 65536
#define KTOT 768
#define CAP  3072
#define THRV 0.18f

// single shared dynamic-smem symbol (gemm + fallback topk)
extern __shared__ unsigned char dynsm[];

// ---------------- scratch (static __device__ = sanctioned alloc-free) -------
__device__ float  g_sim[(size_t)MAXN * MAXS];          // only used by fallback paths
__device__ __half g_At[(size_t)MAXN * KTOT];
__device__ __half g_Bt[(size_t)MAXS * KTOT];
__device__ float  g_candv[(size_t)MAXN * CAP];         // fused-gather candidates
__device__ int    g_candi[(size_t)MAXN * CAP];
__device__ unsigned int g_ccnt[MAXN];
__device__ float  g_topv[MAXN * KSEL];
__device__ int    g_topi[MAXN * KSEL];
__device__ int    g_tkfb[MAXN];                        // fallback flags
__device__ int    g_c1;
__device__ int    g_c5;

__device__ __forceinline__ uint32_t smem_u32(const void* p) {
    uint32_t a;
    asm("{ .reg .u64 t; cvta.to.shared.u64 t, %1; cvt.u32.u64 %0, t; }" : "=r"(a) : "l"(p));
    return a;
}

#define LDSM_X4(r0, r1, r2, r3, addr)                                          \
    asm volatile("ldmatrix.sync.aligned.m8n8.x4.shared.b16 {%0,%1,%2,%3}, [%4];" \
                 : "=r"(r0), "=r"(r1), "=r"(r2), "=r"(r3) : "r"(addr))

#define MMA16816(c, a, b)                                                      \
    asm volatile("mma.sync.aligned.m16n8k16.row.col.f32.f16.f16.f32 "          \
                 "{%0,%1,%2,%3}, {%4,%5,%6,%7}, {%8,%9}, {%0,%1,%2,%3};"       \
                 : "+f"((c)[0]), "+f"((c)[1]), "+f"((c)[2]), "+f"((c)[3])      \
                 : "r"((a)[0]), "r"((a)[1]), "r"((a)[2]), "r"((a)[3]),         \
                   "r"((b)[0]), "r"((b)[1]))

#define CP_ASYNC16(dst, src)                                                   \
    asm volatile("cp.async.cg.shared.global [%0], [%1], 16;" :: "r"(dst), "l"(src))
#define CP_COMMIT() asm volatile("cp.async.commit_group;" ::: "memory")
#define CP_WAIT2()  asm volatile("cp.async.wait_group 2;" ::: "memory")

// ---------------------------------------------------------------------------
// Conversions (fp16 3-term split)
// ---------------------------------------------------------------------------
__global__ void knn_convA(const float* __restrict__ A, int N, int D) {
    int i = blockIdx.x * blockDim.x + threadIdx.x;
    if (i >= N * D) return;
    int m = i / D, k = i - m * D;
    float a = A[i];
    __half h = __float2half_rn(a);
    float hf = __half2float(h);
    __half l = __float2half_rn((a - hf) * 64.f);
    __half h3 = __float2half_rn(hf * (1.f / 32.f));
    size_t ro = (size_t)m * KTOT;
    g_At[ro + k] = h;
    g_At[ro + 256 + k] = l;
    g_At[ro + 512 + k] = h3;
}

__global__ void knn_convB(const float* __restrict__ B, int D, int S) {
    __shared__ float t[32][33];
    int s0 = blockIdx.x * 32, k0 = blockIdx.y * 32;
    t[threadIdx.y][threadIdx.x] = B[(size_t)(k0 + threadIdx.y) * S + s0 + threadIdx.x];
    __syncthreads();
    int k = k0 + threadIdx.x, s = s0 + threadIdx.y;
    float b = t[threadIdx.x][threadIdx.y];
    __half h = __float2half_rn(b);
    float hf = __half2float(h);
    __half h2 = __float2half_rn(hf * (1.f / 64.f));
    __half l3 = __float2half_rn((b - hf) * 32.f);
    size_t ro = (size_t)s * KTOT;
    g_Bt[ro + k] = h;
    g_Bt[ro + 256 + k] = h2;
    g_Bt[ro + 512 + k] = l3;
}

// ---------------------------------------------------------------------------
// mma.sync fp16 GEMM with FUSED threshold-gather epilogue.
// CTA 128x128, BK=32, 512 threads (16 warps, 4Mx4N), warp tile 32x32,
// 4-stage cp.async (&3 indexing), 2 CTAs/SM.
// ---------------------------------------------------------------------------
#define BMT 128
#define BNT 128
#define BKT 32
#define ROWB 80
#define TSZ  (BMT * ROWB)
#define STGB (2 * TSZ)
#define NSTG 4
#define KT   (KTOT / BKT)

__device__ __forceinline__ void gload_stage(uint32_t sbase, int m0, int n0,
                                            int kb, int t) {
    int r = t >> 2, cch = t & 3;
    uint32_t dstA = sbase + r * ROWB + cch * 16;
    const __half* srcA = g_At + (size_t)(m0 + r) * KTOT + kb + cch * 8;
    CP_ASYNC16(dstA, srcA);
    uint32_t dstB = sbase + TSZ + r * ROWB + cch * 16;
    const __half* srcB = g_Bt + (size_t)(n0 + r) * KTOT + kb + cch * 8;
    CP_ASYNC16(dstB, srcB);
}

__device__ __forceinline__ void cand_push(int row, int col, float v) {
    if (v > THRV) {
        unsigned p = atomicAdd(&g_ccnt[row], 1u);
        if (p < CAP) {
            g_candv[(size_t)row * CAP + p] = v;
            g_candi[(size_t)row * CAP + p] = col;
        }
    }
}

__global__ __launch_bounds__(512, 2) void knn_gemm_mma(int S) {
    const uint32_t base = smem_u32(dynsm);
    const int t = threadIdx.x;
    const int wid = t >> 5, l = t & 31;
    const int wm = wid & 3, wn = wid >> 2;
    const int m0 = blockIdx.x * BMT;
    const int n0 = blockIdx.y * BNT;

    float c[2][4][4];
#pragma unroll
    for (int i = 0; i < 2; i++)
#pragma unroll
        for (int j = 0; j < 4; j++)
#pragma unroll
            for (int q = 0; q < 4; q++) c[i][j][q] = 0.f;

    const uint32_t a_row = wm * 32 + (l & 15);
    const uint32_t a_col = (l >> 4) * 8;
    const uint32_t b_row = wn * 32 + (l & 7) + ((l >> 4) & 1) * 8;
    const uint32_t b_col = ((l >> 3) & 1) * 8;

    gload_stage(base, m0, n0, 0, t);                  CP_COMMIT();
    gload_stage(base + STGB, m0, n0, BKT, t);         CP_COMMIT();
    gload_stage(base + 2 * STGB, m0, n0, 2 * BKT, t); CP_COMMIT();

    for (int kt = 0; kt < KT; kt++) {
        CP_WAIT2();
        __syncthreads();
        int nxt = kt + 3;
        if (nxt < KT) gload_stage(base + (nxt & 3) * STGB, m0, n0, nxt * BKT, t);
        CP_COMMIT();

        const uint32_t sa = base + (kt & 3) * STGB;
        const uint32_t sb = sa + TSZ;
#pragma unroll
        for (int ks = 0; ks < 2; ks++) {
            uint32_t a[2][4], b[4][2];
#pragma unroll
            for (int mt = 0; mt < 2; mt++) {
                uint32_t ad = sa + (a_row + mt * 16) * ROWB + (a_col + ks * 16) * 2;
                LDSM_X4(a[mt][0], a[mt][1], a[mt][2], a[mt][3], ad);
            }
#pragma unroll
            for (int np = 0; np < 2; np++) {
                uint32_t bd = sb + (b_row + np * 16) * ROWB + (b_col + ks * 16) * 2;
                uint32_t r0, r1, r2, r3;
                LDSM_X4(r0, r1, r2, r3, bd);
                b[np * 2][0] = r0; b[np * 2][1] = r1;
                b[np * 2 + 1][0] = r2; b[np * 2 + 1][1] = r3;
            }
#pragma unroll
            for (int mt = 0; mt < 2; mt++)
#pragma unroll
                for (int nt = 0; nt < 4; nt++)
                    MMA16816(c[mt][nt], a[mt], b[nt]);
        }
    }

    // ---- fused epilogue with early-out ----
    float mx = c[0][0][0];
#pragma unroll
    for (int mt = 0; mt < 2; mt++)
#pragma unroll
        for (int nt = 0; nt < 4; nt++)
#pragma unroll
            for (int q = 0; q < 4; q++) mx = fmaxf(mx, c[mt][nt][q]);

    if (mx > THRV) {
        const int grp = l >> 2, qd = l & 3;
#pragma unroll
        for (int mt = 0; mt < 2; mt++) {
            int m = m0 + wm * 32 + mt * 16 + grp;
#pragma unroll
            for (int nt = 0; nt < 4; nt++) {
                int n = n0 + wn * 32 + nt * 8 + qd * 2;
                cand_push(m,     n,     c[mt][nt][0]);
                cand_push(m,     n + 1, c[mt][nt][1]);
                cand_push(m + 8, n,     c[mt][nt][2]);
                cand_push(m + 8, n + 1, c[mt][nt][3]);
            }
        }
    }
}

// ---------------------------------------------------------------------------
// Selection: exact top-32 from gathered candidates (desc, index-asc ties).
// Flags rows whose candidate set is unusable (cnt<32 or overflow).
// ---------------------------------------------------------------------------
__global__ __launch_bounds__(256) void knn_sel(int S) {
    __shared__ float cv[CAP];
    __shared__ int   ci[CAP];
    __shared__ float swv[8];
    __shared__ int   swi[8], swp[8];
    const int row = blockIdx.x;
    const int t = threadIdx.x, w = t >> 5, l = t & 31;
    const float NEGINF = __int_as_float(0xff800000);

    unsigned cnt = g_ccnt[row];
    if (cnt < KSEL || cnt > CAP) {
        if (t == 0) g_tkfb[row] = 1;
        return;
    }
    const int M = (int)cnt;
    for (int i = t; i < M; i += 256) {
        cv[i] = g_candv[(size_t)row * CAP + i];
        ci[i] = g_candi[(size_t)row * CAP + i];
    }
    __syncthreads();

    for (int sel = 0; sel < KSEL; sel++) {
        float v = NEGINF; int idx = INT_MAX, pos = -1;
        for (int i = t; i < M; i += 256) {
            float u = cv[i]; int ui = ci[i];
            if (u > v || (u == v && ui < idx)) { v = u; idx = ui; pos = i; }
        }
#pragma unroll
        for (int off = 16; off; off >>= 1) {
            float ov = __shfl_xor_sync(0xffffffffu, v, off);
            int   oi = __shfl_xor_sync(0xffffffffu, idx, off);
            int   op = __shfl_xor_sync(0xffffffffu, pos, off);
            if (ov > v || (ov == v && oi < idx)) { v = ov; idx = oi; pos = op; }
        }
        if (l == 0) { swv[w] = v; swi[w] = idx; swp[w] = pos; }
        __syncthreads();
        if (w == 0) {
            float v2 = (l < 8) ? swv[l] : NEGINF;
            int i2 = (l < 8) ? swi[l] : INT_MAX;
            int p2 = (l < 8) ? swp[l] : -1;
#pragma unroll
            for (int off = 4; off; off >>= 1) {
                float ov = __shfl_xor_sync(0xffffffffu, v2, off);
                int   oi = __shfl_xor_sync(0xffffffffu, i2, off);
                int   op = __shfl_xor_sync(0xffffffffu, p2, off);
                if (ov > v2 || (ov == v2 && oi < i2)) { v2 = ov; i2 = oi; p2 = op; }
            }
            if (l == 0) {
                g_topv[row * KSEL + sel] = v2;
                g_topi[row * KSEL + sel] = i2;
                cv[p2] = NEGINF; ci[p2] = INT_MAX;
            }
        }
        __syncthreads();
    }
}

// ---------------------------------------------------------------------------
// Fallback stage 1: recompute sims (fp32) for flagged rows into g_sim.
// ---------------------------------------------------------------------------
__global__ __launch_bounds__(256) void knn_row_gemv(const float* __restrict__ A,
                                                    const float* __restrict__ B,
                                                    int D, int S) {
    const int row = blockIdx.x;
    if (g_tkfb[row] == 0) return;
    __shared__ float a[256];
    const int t = threadIdx.x;
    for (int k = t; k < D; k += 256) a[k] = A[(size_t)row * D + k];
    __syncthreads();
    for (int s = t; s < S; s += 256) {
        float acc = 0.f;
        for (int k = 0; k < D; k++) acc += a[k] * B[(size_t)k * S + s];
        g_sim[(size_t)row * S + s] = acc;
    }
}

// ---------------------------------------------------------------------------
// Fallback stage 2 / non-fast path: exact insertion top-32 over g_sim.
// ---------------------------------------------------------------------------
#define TKNT 256
__device__ __forceinline__ void warg(float& v, int& idx, int& ln) {
#pragma unroll
    for (int off = 16; off; off >>= 1) {
        float ov = __shfl_xor_sync(0xffffffffu, v, off);
        int   oi = __shfl_xor_sync(0xffffffffu, idx, off);
        int   ol = __shfl_xor_sync(0xffffffffu, ln, off);
        if (ov > v || (ov == v && oi < idx)) { v = ov; idx = oi; ln = ol; }
    }
}

__global__ __launch_bounds__(TKNT) void knn_topk(int S, int force) {
    const int row = blockIdx.x;
    if (!force && g_tkfb[row] == 0) return;

    float* sv = (float*)dynsm;
    int*   si = (int*)(dynsm + TKNT * KSEL * 4);
    float* wv2 = (float*)(dynsm + TKNT * KSEL * 8);
    int*   wi2 = (int*)(dynsm + TKNT * KSEL * 8 + 1024);

    const int t = threadIdx.x;
    const int w = t >> 5, l = t & 31;
    const float* srow = g_sim + (size_t)row * S;
    const float NEGINF = __int_as_float(0xff800000);

    float gmin[8];
#pragma unroll
    for (int it = 0; it < 8; it++) {
        int s = it * (TKNT * 4) + t * 4;
        float4 v4 = *(const float4*)(srow + s);
        float vq[4] = {v4.x, v4.y, v4.z, v4.w};
#pragma unroll
        for (int q = 0; q < 4; q++) {
            int j = it * 4 + q;
            sv[j * TKNT + t] = vq[q];
            si[j * TKNT + t] = s + q;
        }
        gmin[it] = fminf(fminf(vq[0], vq[1]), fminf(vq[2], vq[3]));
    }
    float lmin = gmin[0];
#pragma unroll
    for (int g = 1; g < 8; g++) lmin = fminf(lmin, gmin[g]);

    const int ITER = S / (TKNT * 4);
    for (int it = 8; it < ITER; it++) {
        int s = it * (TKNT * 4) + t * 4;
        float4 v4 = *(const float4*)(srow + s);
        float vq[4] = {v4.x, v4.y, v4.z, v4.w};
#pragma unroll
        for (int q = 0; q < 4; q++) {
            float v = vq[q];
            if (v > lmin) {
                int gpos = 0; float m = gmin[0];
#pragma unroll
                for (int g = 1; g < 8; g++)
                    if (gmin[g] < m) { m = gmin[g]; gpos = g; }
                int jb = gpos * 4;
                float u0 = sv[(jb + 0) * TKNT + t];
                float u1 = sv[(jb + 1) * TKNT + t];
                float u2 = sv[(jb + 2) * TKNT + t];
                float u3 = sv[(jb + 3) * TKNT + t];
                int jm = 0; float mm = u0;
                if (u1 < mm) { mm = u1; jm = 1; }
                if (u2 < mm) { mm = u2; jm = 2; }
                if (u3 < mm) { mm = u3; jm = 3; }
                sv[(jb + jm) * TKNT + t] = v;
                si[(jb + jm) * TKNT + t] = s + q;
                u0 = (jm == 0) ? v : u0;
                u1 = (jm == 1) ? v : u1;
                u2 = (jm == 2) ? v : u2;
                u3 = (jm == 3) ? v : u3;
                float ng = fminf(fminf(u0, u1), fminf(u2, u3));
#pragma unroll
                for (int g = 0; g < 8; g++) if (g == gpos) gmin[g] = ng;
                lmin = gmin[0];
#pragma unroll
                for (int g = 1; g < 8; g++) lmin = fminf(lmin, gmin[g]);
            }
        }
    }
    __syncthreads();

    float bv = NEGINF; int bj = 0, bidx = INT_MAX;
#pragma unroll
    for (int j = 0; j < KSEL; j++) {
        float u = sv[j * TKNT + t]; int ui = si[j * TKNT + t];
        if (u > bv || (u == bv && ui < bidx)) { bv = u; bj = j; bidx = ui; }
    }
    for (int sel = 0; sel < KSEL; sel++) {
        float v = bv; int idx = bidx; int ln = l;
        warg(v, idx, ln);
        if (l == 0) { wv2[w * KSEL + sel] = v; wi2[w * KSEL + sel] = idx; }
        if (l == ln) {
            sv[bj * TKNT + t] = NEGINF; si[bj * TKNT + t] = INT_MAX;
            bv = NEGINF; bj = 0; bidx = INT_MAX;
#pragma unroll
            for (int j = 0; j < KSEL; j++) {
                float u = sv[j * TKNT + t]; int ui = si[j * TKNT + t];
                if (u > bv || (u == bv && ui < bidx)) { bv = u; bj = j; bidx = ui; }
            }
        }
        __syncwarp();
    }
    __syncthreads();

    if (w == 0) {
        int head = 0;
        float hv = NEGINF; int hi = INT_MAX;
        if (l < 8) { hv = wv2[l * KSEL]; hi = wi2[l * KSEL]; }
        for (int sel = 0; sel < KSEL; sel++) {
            float v = hv; int idx = hi; int ln = l;
            warg(v, idx, ln);
            if (l == 0) {
                g_topv[row * KSEL + sel] = v;
                g_topi[row * KSEL + sel] = idx;
            }
            if (l == ln) {
                head++;
                if (l < 8 && head < KSEL) { hv = wv2[l * KSEL + head]; hi = wi2[l * KSEL + head]; }
                else { hv = NEGINF; hi = INT_MAX; }
            }
            __syncwarp();
        }
    }
}

// ---------------------------------------------------------------------------
// Fallback fp32 GEMM (only for unexpected dims) — writes g_sim
// ---------------------------------------------------------------------------
#define BM 64
#define BN 64
#define BK 16
__global__ __launch_bounds__(256) void knn_gemm(const float* __restrict__ A,
                                                const float* __restrict__ B,
                                                int N, int D, int S) {
    __shared__ float As[BK][BM];
    __shared__ float Bs[BK][BN];
    const int tid = threadIdx.x;
    const int tx = tid & 15, ty = tid >> 4;
    const int s0 = blockIdx.x * BN, m0 = blockIdx.y * BM;
    const int am = tid >> 2, ak = (tid & 3) << 2;
    const int bkr = tid >> 4, bc = (tid & 15) << 2;
    float acc[4][4];
#pragma unroll
    for (int i = 0; i < 4; i++)
#pragma unroll
        for (int j = 0; j < 4; j++) acc[i][j] = 0.f;
    const float* aptr = A + (size_t)(m0 + am) * D + ak;
    const float* bptr = B + (size_t)bkr * S + s0 + bc;
    for (int k0 = 0; k0 < D; k0 += BK) {
        float4 av = *(const float4*)(aptr + k0);
        float4 bv = *(const float4*)(bptr + (size_t)k0 * S);
        __syncthreads();
        As[ak + 0][am] = av.x; As[ak + 1][am] = av.y;
        As[ak + 2][am] = av.z; As[ak + 3][am] = av.w;
        *(float4*)&Bs[bkr][bc] = bv;
        __syncthreads();
#pragma unroll
        for (int kk = 0; kk < BK; kk++) {
            float4 a = *(const float4*)&As[kk][ty << 2];
            float4 b = *(const float4*)&Bs[kk][tx << 2];
            acc[0][0] += a.x * b.x; acc[0][1] += a.x * b.y; acc[0][2] += a.x * b.z; acc[0][3] += a.x * b.w;
            acc[1][0] += a.y * b.x; acc[1][1] += a.y * b.y; acc[1][2] += a.y * b.z; acc[1][3] += a.y * b.w;
            acc[2][0] += a.z * b.x; acc[2][1] += a.z * b.y; acc[2][2] += a.z * b.z; acc[2][3] += a.z * b.w;
            acc[3][0] += a.w * b.x; acc[3][1] += a.w * b.y; acc[3][2] += a.w * b.z; acc[3][3] += a.w * b.w;
        }
    }
#pragma unroll
    for (int i = 0; i < 4; i++) {
        float4 v = make_float4(acc[i][0], acc[i][1], acc[i][2], acc[i][3]);
        *(float4*)(g_sim + (size_t)(m0 + (ty << 2) + i) * S + s0 + (tx << 2)) = v;
    }
}

// ---------------------------------------------------------------------------
// Scatter + probs + top-5 accuracy (all rows, from g_topv/g_topi)
// ---------------------------------------------------------------------------
__global__ __launch_bounds__(128) void knn_scatter(const int* __restrict__ qlabels,
                                                   const int* __restrict__ tlabels,
                                                   float* __restrict__ out, int C, int N) {
    __shared__ float p[1024];
    __shared__ float wv[KSEL];
    __shared__ int wc[KSEL];
    __shared__ float rv[128];
    __shared__ int ri[128];
    const int row = blockIdx.x;
    const int t = threadIdx.x;
    const float NEGINF = __int_as_float(0xff800000);

    for (int i = t; i < C; i += 128) p[i] = 0.f;
    if (t < KSEL) {
        float d = g_topv[row * KSEL + t];
        wv[t] = expf(d / 0.07f);
        wc[t] = qlabels[g_topi[row * KSEL + t]];
    }
    __syncthreads();
    if (t == 0) for (int j = 0; j < KSEL; j++) p[wc[j]] += wv[j];
    __syncthreads();
    for (int i = t; i < C; i += 128) out[(size_t)row * C + i] = p[i];

    const int label = tlabels[row];
    int c1 = 0, c5 = 0;
    for (int sel = 0; sel < 5; sel++) {
        float bv = NEGINF; int bi = INT_MAX;
        for (int i = t; i < C; i += 128) {
            float v = p[i];
            if (v > bv || (v == bv && i < bi)) { bv = v; bi = i; }
        }
        rv[t] = bv; ri[t] = bi;
        __syncthreads();
        for (int str = 64; str > 0; str >>= 1) {
            if (t < str) {
                if (rv[t + str] > rv[t] || (rv[t + str] == rv[t] && ri[t + str] < ri[t])) {
                    rv[t] = rv[t + str]; ri[t] = ri[t + str];
                }
            }
            __syncthreads();
        }
        if (t == 0) {
            if (ri[0] == label) { c5++; if (sel == 0) c1++; }
            p[ri[0]] = NEGINF;
        }
        __syncthreads();
    }
    if (t == 0) {
        if (c1) atomicAdd(&g_c1, 1);
        if (c5) atomicAdd(&g_c5, 1);
    }
}

__global__ void knn_init(int N) {
    int i = blockIdx.x * blockDim.x + threadIdx.x;
    if (i < N) { g_tkfb[i] = 0; g_ccnt[i] = 0u; }
    if (i == 0) { g_c1 = 0; g_c5 = 0; }
}
__global__ void knn_final(float* out, size_t off, int N) {
    out[off] = 100.f * (float)g_c1 / (float)N;
    out[off + 1] = 100.f * (float)g_c5 / (float)N;
}

// ---------------------------------------------------------------------------
extern "C" void kernel_launch(void* const* d_in, const int* in_sizes, int n_in,
                              void* d_out, int out_size) {
    const float* feats = (const float*)d_in[0];
    const int* tlabels = (const int*)d_in[1];
    const float* queue = (const float*)d_in[2];
    const int* qlabels = (const int*)d_in[3];

    const int N = in_sizes[1];
    const int D = in_sizes[0] / N;
    const int S = in_sizes[3];
    float* out = (float*)d_out;

    long long os = out_size;
    int C;
    if (N > 0 && (os - 2) > 0 && ((os - 2) % N) == 0) C = (int)((os - 2) / N);
    else C = (int)(os / N);

    const int tk_smem = TKNT * KSEL * 8 + 2048;
    cudaFuncSetAttribute(knn_topk, cudaFuncAttributeMaxDynamicSharedMemorySize, tk_smem);

    const bool fast = (D == 256 && (N % BMT) == 0 && (S % BNT) == 0 && (S % 1024) == 0);

    knn_init<<<(N + 255) / 256, 256>>>(N);

    if (fast) {
        knn_convA<<<(N * D + 255) / 256, 256>>>(feats, N, D);
        knn_convB<<<dim3(S / 32, D / 32), dim3(32, 32)>>>(queue, D, S);
        cudaFuncSetAttribute(knn_gemm_mma,
                             cudaFuncAttributeMaxDynamicSharedMemorySize, NSTG * STGB);
        knn_gemm_mma<<<dim3(N / BMT, S / BNT), 512, NSTG * STGB>>>(S);
        knn_sel<<<N, 256>>>(S);                       // exact select from candidates
        knn_row_gemv<<<N, 256>>>(feats, queue, D, S); // fallback fill (flagged rows)
        knn_topk<<<N, TKNT, tk_smem>>>(S, 0);         // fallback select (flagged rows)
    } else {
        dim3 gg(S / BN, N / BM);
        knn_gemm<<<gg, 256>>>(feats, queue, N, D, S);
        knn_topk<<<N, TKNT, tk_smem>>>(S, 1);
    }

    knn_scatter<<<N, 128>>>(qlabels, tlabels, out, C, N);
    if ((size_t)N * C + 2 <= (size_t)out_size)
        knn_final<<<1, 1>>>(out, (size_t)N * C, N);
}